// round 6
// baseline (speedup 1.0000x reference)
#include <cuda_runtime.h>
#include <math.h>

#define NB 4
#define CC 256
#define HEADS 4
#define DH 64
#define LL 4096
#define GROUPS 32

// Scratch (allocation-free rule: __device__ globals)
__device__ float g_xn[NB * CC * LL];
__device__ float g_q [NB * CC * LL];
__device__ float g_k [NB * CC * LL];
__device__ float g_v [NB * CC * LL];
__device__ float g_ao[NB * CC * LL];
__device__ float g_wt[4 * CC * CC];   // tf32-rounded Wq(*scale),Wk,Wv,Wp

// ---------------------------------------------------------------------------
// helpers
// ---------------------------------------------------------------------------
__device__ __forceinline__ unsigned f2tf(float x) {
    unsigned u;
    asm("cvt.rna.tf32.f32 %0, %1;" : "=r"(u) : "f"(x));
    return u;
}
__device__ __forceinline__ float f2tff(float x) { return __uint_as_float(f2tf(x)); }
__device__ __forceinline__ float ex2f(float x) {
    float r;
    asm("ex2.approx.ftz.f32 %0, %1;" : "=f"(r) : "f"(x));
    return r;
}
__device__ __forceinline__ void mma_tf32(float* c, const unsigned* a,
                                         unsigned b0, unsigned b1) {
    asm volatile(
        "mma.sync.aligned.m16n8k8.row.col.f32.tf32.tf32.f32 "
        "{%0,%1,%2,%3}, {%4,%5,%6,%7}, {%8,%9}, {%0,%1,%2,%3};"
        : "+f"(c[0]), "+f"(c[1]), "+f"(c[2]), "+f"(c[3])
        : "r"(a[0]), "r"(a[1]), "r"(a[2]), "r"(a[3]), "r"(b0), "r"(b1));
}
__device__ __forceinline__ void cp16(float* smem_dst, const float* gmem_src) {
    unsigned sa = (unsigned)__cvta_generic_to_shared(smem_dst);
    asm volatile("cp.async.ca.shared.global [%0], [%1], 16;"
                 :: "r"(sa), "l"(gmem_src) : "memory");
}

// ---------------------------------------------------------------------------
// Weight prep: tf32-round all 4 weight matrices; Wq pre-scaled by
// dh^-0.5 * log2(e) so attention's Q path is a pure copy.
// ---------------------------------------------------------------------------
__global__ void wcvt_kernel(const float* __restrict__ Wq, const float* __restrict__ Wk,
                            const float* __restrict__ Wv, const float* __restrict__ Wp,
                            float* __restrict__ wt) {
    const float qscale = 0.125f * 1.44269504088896340736f;
    int i4 = (blockIdx.x * 256 + threadIdx.x) * 4;
    {
        float4 w = *reinterpret_cast<const float4*>(&Wq[i4]);
        *reinterpret_cast<float4*>(&wt[i4]) =
            make_float4(f2tff(w.x * qscale), f2tff(w.y * qscale),
                        f2tff(w.z * qscale), f2tff(w.w * qscale));
    }
    const float* src[3] = {Wk, Wv, Wp};
    #pragma unroll
    for (int m = 0; m < 3; m++) {
        float4 w = *reinterpret_cast<const float4*>(&src[m][i4]);
        *reinterpret_cast<float4*>(&wt[(m + 1) * CC * CC + i4]) =
            make_float4(f2tff(w.x), f2tff(w.y), f2tff(w.z), f2tff(w.w));
    }
}

// ---------------------------------------------------------------------------
// GroupNorm: one block per (n, group). Output tf32-rounded (feeds tf32 GEMM).
// ---------------------------------------------------------------------------
__global__ void gn_kernel(const float* __restrict__ x,
                          const float* __restrict__ gamma,
                          const float* __restrict__ beta,
                          float* __restrict__ xn) {
    int n = blockIdx.x >> 5;
    int g = blockIdx.x & 31;
    const float* xp = x  + (size_t)(n * CC + g * 8) * LL;
    float*       op = xn + (size_t)(n * CC + g * 8) * LL;

    float s = 0.f, ss = 0.f;
    for (int i = threadIdx.x; i < 8 * LL; i += 256) {
        float v = xp[i];
        s += v; ss += v * v;
    }
    __shared__ float rs[256], rss[256];
    rs[threadIdx.x] = s; rss[threadIdx.x] = ss;
    __syncthreads();
    for (int o = 128; o > 0; o >>= 1) {
        if (threadIdx.x < o) {
            rs[threadIdx.x]  += rs[threadIdx.x + o];
            rss[threadIdx.x] += rss[threadIdx.x + o];
        }
        __syncthreads();
    }
    const float invN = 1.f / (8.f * LL);
    float mean = rs[0] * invN;
    float var  = rss[0] * invN - mean * mean;
    float inv  = rsqrtf(var + 1e-5f);
    for (int i = threadIdx.x; i < 8 * LL; i += 256) {
        int c = g * 8 + (i >> 12);
        op[i] = f2tff((xp[i] - mean) * inv * gamma[c] + beta[c]);
    }
}

// ---------------------------------------------------------------------------
// Fused QKV projection on tensor cores (tf32). Outputs tf32-rounded so the
// attention kernel needs zero conversions.
// ---------------------------------------------------------------------------
__global__ void __launch_bounds__(128) qkv_tc_kernel(
        const float* __restrict__ xn, const float* __restrict__ wt,
        float* __restrict__ q, float* __restrict__ k, float* __restrict__ v) {
    __shared__ float Xs[32 * 72];
    __shared__ float Ws[3][64 * 40];

    int n  = blockIdx.z;
    int o0 = blockIdx.y << 6;
    int l0 = blockIdx.x << 6;
    const float* xb = xn + (size_t)n * CC * LL;

    int tid = threadIdx.x;
    int lane = tid & 31, w = tid >> 5;
    int g = lane >> 2, t4 = lane & 3;

    float acc[3][8][4];
    #pragma unroll
    for (int m = 0; m < 3; m++)
        #pragma unroll
        for (int nt = 0; nt < 8; nt++)
            #pragma unroll
            for (int c = 0; c < 4; c++) acc[m][nt][c] = 0.f;

    for (int c0 = 0; c0 < CC; c0 += 32) {
        __syncthreads();
        #pragma unroll
        for (int r = 0; r < 4; r++) {
            int idx = r * 512 + tid * 4;
            int cc = idx >> 6, ll = idx & 63;
            float4 xv = *reinterpret_cast<const float4*>(&xb[(size_t)(c0 + cc) * LL + l0 + ll]);
            *reinterpret_cast<float4*>(&Xs[cc * 72 + ll]) = xv;
        }
        #pragma unroll
        for (int m = 0; m < 3; m++) {
            const float* Wm = wt + m * CC * CC;
            #pragma unroll
            for (int p = 0; p < 4; p++) {
                int oo = (tid >> 3) + p * 16;
                int cc4 = (tid & 7) * 4;
                float4 wv = *reinterpret_cast<const float4*>(&Wm[(o0 + oo) * CC + c0 + cc4]);
                *reinterpret_cast<float4*>(&Ws[m][oo * 40 + cc4]) = wv;
            }
        }
        __syncthreads();

        #pragma unroll
        for (int kt = 0; kt < 4; kt++) {
            int kk = kt * 8;
            unsigned a[3][4];
            #pragma unroll
            for (int m = 0; m < 3; m++) {
                a[m][0] = __float_as_uint(Ws[m][(w * 16 + g) * 40 + kk + t4]);
                a[m][1] = __float_as_uint(Ws[m][(w * 16 + g + 8) * 40 + kk + t4]);
                a[m][2] = __float_as_uint(Ws[m][(w * 16 + g) * 40 + kk + t4 + 4]);
                a[m][3] = __float_as_uint(Ws[m][(w * 16 + g + 8) * 40 + kk + t4 + 4]);
            }
            #pragma unroll
            for (int nt = 0; nt < 8; nt++) {
                unsigned b0 = __float_as_uint(Xs[(kk + t4) * 72 + nt * 8 + g]);
                unsigned b1 = __float_as_uint(Xs[(kk + t4 + 4) * 72 + nt * 8 + g]);
                mma_tf32(acc[0][nt], a[0], b0, b1);
                mma_tf32(acc[1][nt], a[1], b0, b1);
                mma_tf32(acc[2][nt], a[2], b0, b1);
            }
        }
    }

    float* outs[3] = {q, k, v};
    int orow = o0 + w * 16 + g;
    #pragma unroll
    for (int m = 0; m < 3; m++) {
        float* op = outs[m] + (size_t)n * CC * LL;
        #pragma unroll
        for (int nt = 0; nt < 8; nt++) {
            size_t base = (size_t)orow * LL + l0 + nt * 8 + 2 * t4;
            *reinterpret_cast<float2*>(&op[base]) =
                make_float2(f2tff(acc[m][nt][0]), f2tff(acc[m][nt][1]));
            *reinterpret_cast<float2*>(&op[base + 8 * LL]) =
                make_float2(f2tff(acc[m][nt][2]), f2tff(acc[m][nt][3]));
        }
    }
}

// ---------------------------------------------------------------------------
// Output projection on tensor cores (tf32) + bias, writes d_out.
// ---------------------------------------------------------------------------
__global__ void __launch_bounds__(128) oproj_tc_kernel(
        const float* __restrict__ ao, const float* __restrict__ wt,
        const float* __restrict__ bias, float* __restrict__ out) {
    __shared__ float Xs[32 * 72];
    __shared__ float Ws[64 * 40];

    int n  = blockIdx.z;
    int o0 = blockIdx.y << 6;
    int l0 = blockIdx.x << 6;
    const float* xb = ao + (size_t)n * CC * LL;

    int tid = threadIdx.x;
    int lane = tid & 31, w = tid >> 5;
    int g = lane >> 2, t4 = lane & 3;

    float acc[8][4];
    #pragma unroll
    for (int nt = 0; nt < 8; nt++)
        #pragma unroll
        for (int c = 0; c < 4; c++) acc[nt][c] = 0.f;

    for (int c0 = 0; c0 < CC; c0 += 32) {
        __syncthreads();
        #pragma unroll
        for (int r = 0; r < 4; r++) {
            int idx = r * 512 + tid * 4;
            int cc = idx >> 6, ll = idx & 63;
            float4 xv = *reinterpret_cast<const float4*>(&xb[(size_t)(c0 + cc) * LL + l0 + ll]);
            *reinterpret_cast<float4*>(&Xs[cc * 72 + ll]) = xv;
        }
        #pragma unroll
        for (int p = 0; p < 4; p++) {
            int oo = (tid >> 3) + p * 16;
            int cc4 = (tid & 7) * 4;
            float4 wv = *reinterpret_cast<const float4*>(&wt[(o0 + oo) * CC + c0 + cc4]);
            *reinterpret_cast<float4*>(&Ws[oo * 40 + cc4]) = wv;
        }
        __syncthreads();

        #pragma unroll
        for (int kt = 0; kt < 4; kt++) {
            int kk = kt * 8;
            unsigned a[4];
            a[0] = __float_as_uint(Ws[(w * 16 + g) * 40 + kk + t4]);
            a[1] = __float_as_uint(Ws[(w * 16 + g + 8) * 40 + kk + t4]);
            a[2] = __float_as_uint(Ws[(w * 16 + g) * 40 + kk + t4 + 4]);
            a[3] = __float_as_uint(Ws[(w * 16 + g + 8) * 40 + kk + t4 + 4]);
            #pragma unroll
            for (int nt = 0; nt < 8; nt++) {
                unsigned b0 = __float_as_uint(Xs[(kk + t4) * 72 + nt * 8 + g]);
                unsigned b1 = __float_as_uint(Xs[(kk + t4 + 4) * 72 + nt * 8 + g]);
                mma_tf32(acc[nt], a, b0, b1);
            }
        }
    }

    int orow = o0 + w * 16 + g;
    float bb0 = bias[orow], bb1 = bias[orow + 8];
    float* op = out + (size_t)n * CC * LL;
    #pragma unroll
    for (int nt = 0; nt < 8; nt++) {
        size_t base = (size_t)orow * LL + l0 + nt * 8 + 2 * t4;
        *reinterpret_cast<float2*>(&op[base]) =
            make_float2(acc[nt][0] + bb0, acc[nt][1] + bb0);
        *reinterpret_cast<float2*>(&op[base + 8 * LL]) =
            make_float2(acc[nt][2] + bb1, acc[nt][3] + bb1);
    }
}

// ---------------------------------------------------------------------------
// Flash attention, tf32 mma, R4 tiling (4 warps x 16 rows), with:
//  - zero conversions in the K/V/Q path (producers pre-round to tf32)
//  - cp.async double-buffered K/V tiles: tile jt+1 streams in during compute
// Smem: Ks[2] (pad 72), Vs[2] (pad 68), QPs (pad 72) = 22528 floats = 88 KB.
// ---------------------------------------------------------------------------
#define PK 72
#define PV 68
#define PP 68
#define NT (LL / 64)

__device__ __forceinline__ void issue_kv(const float* kb, const float* vb,
                                         float* Kbuf, float* Vbuf,
                                         int lk, int tid) {
    #pragma unroll
    for (int r = 0; r < 8; r++) {
        int idx = r * 512 + tid * 4;
        int d = idx >> 6, j = idx & 63;
        cp16(&Kbuf[d * PK + j], &kb[(size_t)d * LL + lk + j]);
        cp16(&Vbuf[d * PV + j], &vb[(size_t)d * LL + lk + j]);
    }
    asm volatile("cp.async.commit_group;" ::: "memory");
}

__global__ void __launch_bounds__(128) attn_tc_kernel(
        const float* __restrict__ q, const float* __restrict__ k,
        const float* __restrict__ v, float* __restrict__ ao) {
    extern __shared__ float sm[];
    float* Ksb[2] = {sm,        sm + 4608};
    float* Vsb[2] = {sm + 9216, sm + 13568};
    float* QPs    = sm + 17920;            // Q [d][i] pad PK, then P [i][j] pad PP

    int nh = blockIdx.y;
    int n = nh >> 2, h = nh & 3;
    int l0 = blockIdx.x << 6;
    const float* qb = q + ((size_t)n * CC + h * DH) * LL;
    const float* kb = k + ((size_t)n * CC + h * DH) * LL;
    const float* vb = v + ((size_t)n * CC + h * DH) * LL;

    int tid  = threadIdx.x;
    int lane = tid & 31, w = tid >> 5;
    int g = lane >> 2, t4 = lane & 3;
    int row0 = w * 16 + g;

    // Kick off tile 0 loads immediately.
    issue_kv(kb, vb, Ksb[0], Vsb[0], 0, tid);

    // Q tile -> QPs[d][i] (pure copy; q is pre-scaled + tf32-rounded)
    #pragma unroll
    for (int r = 0; r < 8; r++) {
        int idx = r * 512 + tid * 4;
        int d = idx >> 6, j = idx & 63;
        float4 xq = *reinterpret_cast<const float4*>(&qb[(size_t)d * LL + l0 + j]);
        *reinterpret_cast<float4*>(&QPs[d * PK + j]) = xq;
    }
    __syncthreads();

    unsigned qa[8][4];
    #pragma unroll
    for (int kt = 0; kt < 8; kt++) {
        int kk = kt * 8 + t4;
        qa[kt][0] = __float_as_uint(QPs[kk * PK + row0]);
        qa[kt][1] = __float_as_uint(QPs[kk * PK + row0 + 8]);
        qa[kt][2] = __float_as_uint(QPs[(kk + 4) * PK + row0]);
        qa[kt][3] = __float_as_uint(QPs[(kk + 4) * PK + row0 + 8]);
    }
    __syncthreads();  // QPs now reusable as Ps

    float m0 = -INFINITY, m1 = -INFINITY, ls0 = 0.f, ls1 = 0.f;
    float o[8][4];
    #pragma unroll
    for (int nt = 0; nt < 8; nt++)
        #pragma unroll
        for (int c = 0; c < 4; c++) o[nt][c] = 0.f;

    for (int jt = 0; jt < NT; jt++) {
        int cur = jt & 1;
        // Stream next tile into the other buffer (safe: it was last read in
        // iteration jt-1, which completed before this point's entry barrier).
        if (jt + 1 < NT) {
            issue_kv(kb, vb, Ksb[cur ^ 1], Vsb[cur ^ 1], (jt + 1) << 6, tid);
            asm volatile("cp.async.wait_group 1;" ::: "memory");
        } else {
            asm volatile("cp.async.wait_group 0;" ::: "memory");
        }
        __syncthreads();  // tile jt fully visible to all warps

        const float* Ks = Ksb[cur];
        const float* Vs = Vsb[cur];

        // ---- S = Q K^T ----
        float s[8][4];
        #pragma unroll
        for (int nt = 0; nt < 8; nt++)
            #pragma unroll
            for (int c = 0; c < 4; c++) s[nt][c] = 0.f;
        #pragma unroll
        for (int kt = 0; kt < 8; kt++) {
            int kk = kt * 8;
            #pragma unroll
            for (int nt = 0; nt < 8; nt++) {
                unsigned b0 = __float_as_uint(Ks[(kk + t4) * PK + nt * 8 + g]);
                unsigned b1 = __float_as_uint(Ks[(kk + t4 + 4) * PK + nt * 8 + g]);
                mma_tf32(s[nt], qa[kt], b0, b1);
            }
        }

        // ---- online softmax (base-2; scale pre-folded into Wq) ----
        float mx0 = -INFINITY, mx1 = -INFINITY;
        #pragma unroll
        for (int nt = 0; nt < 8; nt++) {
            mx0 = fmaxf(mx0, fmaxf(s[nt][0], s[nt][1]));
            mx1 = fmaxf(mx1, fmaxf(s[nt][2], s[nt][3]));
        }
        mx0 = fmaxf(mx0, __shfl_xor_sync(0xffffffffu, mx0, 1));
        mx0 = fmaxf(mx0, __shfl_xor_sync(0xffffffffu, mx0, 2));
        mx1 = fmaxf(mx1, __shfl_xor_sync(0xffffffffu, mx1, 1));
        mx1 = fmaxf(mx1, __shfl_xor_sync(0xffffffffu, mx1, 2));
        float mn0 = fmaxf(m0, mx0), mn1 = fmaxf(m1, mx1);
        float c0 = ex2f(m0 - mn0), c1 = ex2f(m1 - mn1);
        float rs0 = 0.f, rs1 = 0.f;
        float* Ps = QPs;
        #pragma unroll
        for (int nt = 0; nt < 8; nt++) {
            float p00 = ex2f(s[nt][0] - mn0);
            float p01 = ex2f(s[nt][1] - mn0);
            float p10 = ex2f(s[nt][2] - mn1);
            float p11 = ex2f(s[nt][3] - mn1);
            rs0 += p00 + p01;
            rs1 += p10 + p11;
            int colc = nt * 8 + 2 * t4;
            *reinterpret_cast<float2*>(&Ps[row0 * PP + colc]) =
                make_float2(f2tff(p00), f2tff(p01));
            *reinterpret_cast<float2*>(&Ps[(row0 + 8) * PP + colc]) =
                make_float2(f2tff(p10), f2tff(p11));
        }
        rs0 += __shfl_xor_sync(0xffffffffu, rs0, 1);
        rs0 += __shfl_xor_sync(0xffffffffu, rs0, 2);
        rs1 += __shfl_xor_sync(0xffffffffu, rs1, 1);
        rs1 += __shfl_xor_sync(0xffffffffu, rs1, 2);
        ls0 = ls0 * c0 + rs0;
        ls1 = ls1 * c1 + rs1;
        m0 = mn0; m1 = mn1;
        #pragma unroll
        for (int nt = 0; nt < 8; nt++) {
            o[nt][0] *= c0; o[nt][1] *= c0;
            o[nt][2] *= c1; o[nt][3] *= c1;
        }
        __syncwarp();  // P rows are warp-local

        // ---- O += P V ----
        #pragma unroll
        for (int kt = 0; kt < 8; kt++) {
            int kk = kt * 8;
            unsigned a[4];
            a[0] = __float_as_uint(Ps[row0 * PP + kk + t4]);
            a[1] = __float_as_uint(Ps[(row0 + 8) * PP + kk + t4]);
            a[2] = __float_as_uint(Ps[row0 * PP + kk + t4 + 4]);
            a[3] = __float_as_uint(Ps[(row0 + 8) * PP + kk + t4 + 4]);
            #pragma unroll
            for (int nt = 0; nt < 8; nt++) {
                unsigned b0 = __float_as_uint(Vs[(nt * 8 + g) * PV + kk + t4]);
                unsigned b1 = __float_as_uint(Vs[(nt * 8 + g) * PV + kk + t4 + 4]);
                mma_tf32(o[nt], a, b0, b1);
            }
        }
        __syncthreads();  // all warps done reading Ks/Vs[cur] (next issue reuses it)
    }

    // ---- normalize, stage O^T [d][i] (pad PV) in Ks0 region, write tf32 ----
    float inv0 = 1.f / ls0, inv1 = 1.f / ls1;
    float* Os = Ksb[0];
    #pragma unroll
    for (int nt = 0; nt < 8; nt++) {
        int d = nt * 8 + 2 * t4;
        Os[(d    ) * PV + row0]     = f2tff(o[nt][0] * inv0);
        Os[(d + 1) * PV + row0]     = f2tff(o[nt][1] * inv0);
        Os[(d    ) * PV + row0 + 8] = f2tff(o[nt][2] * inv1);
        Os[(d + 1) * PV + row0 + 8] = f2tff(o[nt][3] * inv1);
    }
    __syncthreads();
    const size_t cbase = (size_t)n * CC + h * DH;
    #pragma unroll
    for (int r = 0; r < 8; r++) {
        int idx = r * 512 + tid * 4;
        int d = idx >> 6, i = idx & 63;
        float4 val = *reinterpret_cast<const float4*>(&Os[d * PV + i]);
        *reinterpret_cast<float4*>(&ao[(cbase + d) * LL + l0 + i]) = val;
    }
}

// ---------------------------------------------------------------------------
extern "C" void kernel_launch(void* const* d_in, const int* in_sizes, int n_in,
                              void* d_out, int out_size) {
    const float* x     = (const float*)d_in[0];
    const float* gamma = (const float*)d_in[1];
    const float* beta  = (const float*)d_in[2];
    const float* Wq    = (const float*)d_in[3];
    const float* Wk    = (const float*)d_in[4];
    const float* Wv    = (const float*)d_in[5];
    const float* Wp    = (const float*)d_in[6];
    const float* bp    = (const float*)d_in[7];
    float* out = (float*)d_out;

    static float *xn = nullptr, *q, *k, *v, *ao, *wt;
    static size_t attn_smem = (size_t)22528 * sizeof(float);  // 90112 B
    if (!xn) {
        cudaGetSymbolAddress((void**)&xn, g_xn);
        cudaGetSymbolAddress((void**)&q,  g_q);
        cudaGetSymbolAddress((void**)&k,  g_k);
        cudaGetSymbolAddress((void**)&v,  g_v);
        cudaGetSymbolAddress((void**)&ao, g_ao);
        cudaGetSymbolAddress((void**)&wt, g_wt);
        cudaFuncSetAttribute(attn_tc_kernel,
                             cudaFuncAttributeMaxDynamicSharedMemorySize,
                             (int)attn_smem);
    }

    // Weight tf32 prep (+Wq scaling) + GroupNorm (independent)
    wcvt_kernel<<<CC * CC / (256 * 4), 256>>>(Wq, Wk, Wv, Wp, wt);
    gn_kernel<<<NB * GROUPS, 256>>>(x, gamma, beta, xn);

    // Fused QKV projection (tensor cores, outputs tf32-rounded)
    dim3 pgrid(LL / 64, CC / 64, NB);
    qkv_tc_kernel<<<pgrid, 128>>>(xn, wt, q, k, v);

    // Flash attention (tensor cores, cp.async double-buffered K/V)
    attn_tc_kernel<<<dim3(LL / 64, NB * HEADS), 128, attn_smem>>>(q, k, v, ao);

    // Output projection (+bias) straight into d_out (tensor cores)
    oproj_tc_kernel<<<pgrid, 128>>>(ao, wt + 3 * CC * CC, bp, out);
}

// round 7
// speedup vs baseline: 1.2013x; 1.2013x over previous
#include <cuda_runtime.h>
#include <math.h>

#define NB 4
#define CC 256
#define HEADS 4
#define DH 64
#define LL 4096
#define GROUPS 32

// Scratch (allocation-free rule: __device__ globals)
__device__ float g_xn[NB * CC * LL];
__device__ float g_q [NB * CC * LL];
__device__ float g_k [NB * CC * LL];
__device__ float g_v [NB * CC * LL];
__device__ float g_ao[NB * CC * LL];
__device__ float g_wt[4 * CC * CC];   // tf32-rounded Wq(*scale),Wk,Wv,Wp

// ---------------------------------------------------------------------------
// helpers
// ---------------------------------------------------------------------------
__device__ __forceinline__ unsigned f2tf(float x) {
    unsigned u;
    asm("cvt.rna.tf32.f32 %0, %1;" : "=r"(u) : "f"(x));
    return u;
}
__device__ __forceinline__ float f2tff(float x) { return __uint_as_float(f2tf(x)); }
__device__ __forceinline__ float ex2f(float x) {
    float r;
    asm("ex2.approx.ftz.f32 %0, %1;" : "=f"(r) : "f"(x));
    return r;
}
__device__ __forceinline__ void mma_tf32(float* c, const unsigned* a,
                                         unsigned b0, unsigned b1) {
    asm volatile(
        "mma.sync.aligned.m16n8k8.row.col.f32.tf32.tf32.f32 "
        "{%0,%1,%2,%3}, {%4,%5,%6,%7}, {%8,%9}, {%0,%1,%2,%3};"
        : "+f"(c[0]), "+f"(c[1]), "+f"(c[2]), "+f"(c[3])
        : "r"(a[0]), "r"(a[1]), "r"(a[2]), "r"(a[3]), "r"(b0), "r"(b1));
}
__device__ __forceinline__ void cp16(float* smem_dst, const float* gmem_src) {
    unsigned sa = (unsigned)__cvta_generic_to_shared(smem_dst);
    asm volatile("cp.async.ca.shared.global [%0], [%1], 16;"
                 :: "r"(sa), "l"(gmem_src) : "memory");
}

// ---------------------------------------------------------------------------
// Weight prep: tf32-round all 4 weight matrices; Wq pre-scaled by
// dh^-0.5 * log2(e) so attention's Q path is a pure copy.
// ---------------------------------------------------------------------------
__global__ void wcvt_kernel(const float* __restrict__ Wq, const float* __restrict__ Wk,
                            const float* __restrict__ Wv, const float* __restrict__ Wp,
                            float* __restrict__ wt) {
    const float qscale = 0.125f * 1.44269504088896340736f;
    int i4 = (blockIdx.x * 256 + threadIdx.x) * 4;
    {
        float4 w = *reinterpret_cast<const float4*>(&Wq[i4]);
        *reinterpret_cast<float4*>(&wt[i4]) =
            make_float4(f2tff(w.x * qscale), f2tff(w.y * qscale),
                        f2tff(w.z * qscale), f2tff(w.w * qscale));
    }
    const float* src[3] = {Wk, Wv, Wp};
    #pragma unroll
    for (int m = 0; m < 3; m++) {
        float4 w = *reinterpret_cast<const float4*>(&src[m][i4]);
        *reinterpret_cast<float4*>(&wt[(m + 1) * CC * CC + i4]) =
            make_float4(f2tff(w.x), f2tff(w.y), f2tff(w.z), f2tff(w.w));
    }
}

// ---------------------------------------------------------------------------
// GroupNorm: one block per (n, group). Output tf32-rounded (feeds tf32 GEMM).
// ---------------------------------------------------------------------------
__global__ void gn_kernel(const float* __restrict__ x,
                          const float* __restrict__ gamma,
                          const float* __restrict__ beta,
                          float* __restrict__ xn) {
    int n = blockIdx.x >> 5;
    int g = blockIdx.x & 31;
    const float* xp = x  + (size_t)(n * CC + g * 8) * LL;
    float*       op = xn + (size_t)(n * CC + g * 8) * LL;

    float s = 0.f, ss = 0.f;
    for (int i = threadIdx.x; i < 8 * LL; i += 256) {
        float v = xp[i];
        s += v; ss += v * v;
    }
    __shared__ float rs[256], rss[256];
    rs[threadIdx.x] = s; rss[threadIdx.x] = ss;
    __syncthreads();
    for (int o = 128; o > 0; o >>= 1) {
        if (threadIdx.x < o) {
            rs[threadIdx.x]  += rs[threadIdx.x + o];
            rss[threadIdx.x] += rss[threadIdx.x + o];
        }
        __syncthreads();
    }
    const float invN = 1.f / (8.f * LL);
    float mean = rs[0] * invN;
    float var  = rss[0] * invN - mean * mean;
    float inv  = rsqrtf(var + 1e-5f);
    for (int i = threadIdx.x; i < 8 * LL; i += 256) {
        int c = g * 8 + (i >> 12);
        op[i] = f2tff((xp[i] - mean) * inv * gamma[c] + beta[c]);
    }
}

// ---------------------------------------------------------------------------
// Fused QKV projection on tensor cores (tf32). Outputs tf32-rounded so the
// attention kernel needs zero conversions.
// ---------------------------------------------------------------------------
__global__ void __launch_bounds__(128) qkv_tc_kernel(
        const float* __restrict__ xn, const float* __restrict__ wt,
        float* __restrict__ q, float* __restrict__ k, float* __restrict__ v) {
    __shared__ float Xs[32 * 72];
    __shared__ float Ws[3][64 * 40];

    int n  = blockIdx.z;
    int o0 = blockIdx.y << 6;
    int l0 = blockIdx.x << 6;
    const float* xb = xn + (size_t)n * CC * LL;

    int tid = threadIdx.x;
    int lane = tid & 31, w = tid >> 5;
    int g = lane >> 2, t4 = lane & 3;

    float acc[3][8][4];
    #pragma unroll
    for (int m = 0; m < 3; m++)
        #pragma unroll
        for (int nt = 0; nt < 8; nt++)
            #pragma unroll
            for (int c = 0; c < 4; c++) acc[m][nt][c] = 0.f;

    for (int c0 = 0; c0 < CC; c0 += 32) {
        __syncthreads();
        #pragma unroll
        for (int r = 0; r < 4; r++) {
            int idx = r * 512 + tid * 4;
            int cc = idx >> 6, ll = idx & 63;
            float4 xv = *reinterpret_cast<const float4*>(&xb[(size_t)(c0 + cc) * LL + l0 + ll]);
            *reinterpret_cast<float4*>(&Xs[cc * 72 + ll]) = xv;
        }
        #pragma unroll
        for (int m = 0; m < 3; m++) {
            const float* Wm = wt + m * CC * CC;
            #pragma unroll
            for (int p = 0; p < 4; p++) {
                int oo = (tid >> 3) + p * 16;
                int cc4 = (tid & 7) * 4;
                float4 wv = *reinterpret_cast<const float4*>(&Wm[(o0 + oo) * CC + c0 + cc4]);
                *reinterpret_cast<float4*>(&Ws[m][oo * 40 + cc4]) = wv;
            }
        }
        __syncthreads();

        #pragma unroll
        for (int kt = 0; kt < 4; kt++) {
            int kk = kt * 8;
            unsigned a[3][4];
            #pragma unroll
            for (int m = 0; m < 3; m++) {
                a[m][0] = __float_as_uint(Ws[m][(w * 16 + g) * 40 + kk + t4]);
                a[m][1] = __float_as_uint(Ws[m][(w * 16 + g + 8) * 40 + kk + t4]);
                a[m][2] = __float_as_uint(Ws[m][(w * 16 + g) * 40 + kk + t4 + 4]);
                a[m][3] = __float_as_uint(Ws[m][(w * 16 + g + 8) * 40 + kk + t4 + 4]);
            }
            #pragma unroll
            for (int nt = 0; nt < 8; nt++) {
                unsigned b0 = __float_as_uint(Xs[(kk + t4) * 72 + nt * 8 + g]);
                unsigned b1 = __float_as_uint(Xs[(kk + t4 + 4) * 72 + nt * 8 + g]);
                mma_tf32(acc[0][nt], a[0], b0, b1);
                mma_tf32(acc[1][nt], a[1], b0, b1);
                mma_tf32(acc[2][nt], a[2], b0, b1);
            }
        }
    }

    float* outs[3] = {q, k, v};
    int orow = o0 + w * 16 + g;
    #pragma unroll
    for (int m = 0; m < 3; m++) {
        float* op = outs[m] + (size_t)n * CC * LL;
        #pragma unroll
        for (int nt = 0; nt < 8; nt++) {
            size_t base = (size_t)orow * LL + l0 + nt * 8 + 2 * t4;
            *reinterpret_cast<float2*>(&op[base]) =
                make_float2(f2tff(acc[m][nt][0]), f2tff(acc[m][nt][1]));
            *reinterpret_cast<float2*>(&op[base + 8 * LL]) =
                make_float2(f2tff(acc[m][nt][2]), f2tff(acc[m][nt][3]));
        }
    }
}

// ---------------------------------------------------------------------------
// Output projection on tensor cores (tf32) + bias, writes d_out.
// ---------------------------------------------------------------------------
__global__ void __launch_bounds__(128) oproj_tc_kernel(
        const float* __restrict__ ao, const float* __restrict__ wt,
        const float* __restrict__ bias, float* __restrict__ out) {
    __shared__ float Xs[32 * 72];
    __shared__ float Ws[64 * 40];

    int n  = blockIdx.z;
    int o0 = blockIdx.y << 6;
    int l0 = blockIdx.x << 6;
    const float* xb = ao + (size_t)n * CC * LL;

    int tid = threadIdx.x;
    int lane = tid & 31, w = tid >> 5;
    int g = lane >> 2, t4 = lane & 3;

    float acc[8][4];
    #pragma unroll
    for (int nt = 0; nt < 8; nt++)
        #pragma unroll
        for (int c = 0; c < 4; c++) acc[nt][c] = 0.f;

    for (int c0 = 0; c0 < CC; c0 += 32) {
        __syncthreads();
        #pragma unroll
        for (int r = 0; r < 4; r++) {
            int idx = r * 512 + tid * 4;
            int cc = idx >> 6, ll = idx & 63;
            float4 xv = *reinterpret_cast<const float4*>(&xb[(size_t)(c0 + cc) * LL + l0 + ll]);
            *reinterpret_cast<float4*>(&Xs[cc * 72 + ll]) = xv;
        }
        #pragma unroll
        for (int p = 0; p < 4; p++) {
            int oo = (tid >> 3) + p * 16;
            int cc4 = (tid & 7) * 4;
            float4 wv = *reinterpret_cast<const float4*>(&wt[(o0 + oo) * CC + c0 + cc4]);
            *reinterpret_cast<float4*>(&Ws[oo * 40 + cc4]) = wv;
        }
        __syncthreads();

        #pragma unroll
        for (int kt = 0; kt < 4; kt++) {
            int kk = kt * 8;
            unsigned a[4];
            a[0] = __float_as_uint(Ws[(w * 16 + g) * 40 + kk + t4]);
            a[1] = __float_as_uint(Ws[(w * 16 + g + 8) * 40 + kk + t4]);
            a[2] = __float_as_uint(Ws[(w * 16 + g) * 40 + kk + t4 + 4]);
            a[3] = __float_as_uint(Ws[(w * 16 + g + 8) * 40 + kk + t4 + 4]);
            #pragma unroll
            for (int nt = 0; nt < 8; nt++) {
                unsigned b0 = __float_as_uint(Xs[(kk + t4) * 72 + nt * 8 + g]);
                unsigned b1 = __float_as_uint(Xs[(kk + t4 + 4) * 72 + nt * 8 + g]);
                mma_tf32(acc[nt], a, b0, b1);
            }
        }
    }

    int orow = o0 + w * 16 + g;
    float bb0 = bias[orow], bb1 = bias[orow + 8];
    float* op = out + (size_t)n * CC * LL;
    #pragma unroll
    for (int nt = 0; nt < 8; nt++) {
        size_t base = (size_t)orow * LL + l0 + nt * 8 + 2 * t4;
        *reinterpret_cast<float2*>(&op[base]) =
            make_float2(acc[nt][0] + bb0, acc[nt][1] + bb0);
        *reinterpret_cast<float2*>(&op[base + 8 * LL]) =
            make_float2(acc[nt][2] + bb1, acc[nt][3] + bb1);
    }
}

// ---------------------------------------------------------------------------
// Flash attention: R4 tiling (4 warps x 16 rows, 54 KB smem -> 4 blocks/SM)
// + CVT-free loads (producers pre-round to tf32) via cp.async pure copies.
// ---------------------------------------------------------------------------
#define PK 72
#define PV 68
#define PP 68
#define NT (LL / 64)

__global__ void __launch_bounds__(128) attn_tc_kernel(
        const float* __restrict__ q, const float* __restrict__ k,
        const float* __restrict__ v, float* __restrict__ ao) {
    extern __shared__ float sm[];
    float* Ks  = sm;                 // [d][j] pad PK (also O^T staging at end)
    float* Vs  = sm + 64 * PK;       // [d][j] pad PV
    float* QPs = Vs + 64 * PV;       // Q [d][i] pad PK, then P [i][j] pad PP

    int nh = blockIdx.y;
    int n = nh >> 2, h = nh & 3;
    int l0 = blockIdx.x << 6;
    const float* qb = q + ((size_t)n * CC + h * DH) * LL;
    const float* kb = k + ((size_t)n * CC + h * DH) * LL;
    const float* vb = v + ((size_t)n * CC + h * DH) * LL;

    int tid  = threadIdx.x;
    int lane = tid & 31, w = tid >> 5;
    int g = lane >> 2, t4 = lane & 3;
    int row0 = w * 16 + g;

    // Q tile -> QPs[d][i] via cp.async (pure copy; pre-scaled + tf32-rounded)
    #pragma unroll
    for (int r = 0; r < 8; r++) {
        int idx = r * 512 + tid * 4;
        int d = idx >> 6, j = idx & 63;
        cp16(&QPs[d * PK + j], &qb[(size_t)d * LL + l0 + j]);
    }
    asm volatile("cp.async.commit_group;" ::: "memory");
    asm volatile("cp.async.wait_group 0;" ::: "memory");
    __syncthreads();

    unsigned qa[8][4];
    #pragma unroll
    for (int kt = 0; kt < 8; kt++) {
        int kk = kt * 8 + t4;
        qa[kt][0] = __float_as_uint(QPs[kk * PK + row0]);
        qa[kt][1] = __float_as_uint(QPs[kk * PK + row0 + 8]);
        qa[kt][2] = __float_as_uint(QPs[(kk + 4) * PK + row0]);
        qa[kt][3] = __float_as_uint(QPs[(kk + 4) * PK + row0 + 8]);
    }
    __syncthreads();  // QPs now reusable as Ps

    float m0 = -INFINITY, m1 = -INFINITY, ls0 = 0.f, ls1 = 0.f;
    float o[8][4];
    #pragma unroll
    for (int nt = 0; nt < 8; nt++)
        #pragma unroll
        for (int c = 0; c < 4; c++) o[nt][c] = 0.f;

    for (int jt = 0; jt < NT; jt++) {
        int lk = jt << 6;
        // ---- K,V tiles via cp.async pure copies ----
        #pragma unroll
        for (int r = 0; r < 8; r++) {
            int idx = r * 512 + tid * 4;
            int d = idx >> 6, j = idx & 63;
            cp16(&Ks[d * PK + j], &kb[(size_t)d * LL + lk + j]);
            cp16(&Vs[d * PV + j], &vb[(size_t)d * LL + lk + j]);
        }
        asm volatile("cp.async.commit_group;" ::: "memory");
        asm volatile("cp.async.wait_group 0;" ::: "memory");
        __syncthreads();

        // ---- S = Q K^T ----
        float s[8][4];
        #pragma unroll
        for (int nt = 0; nt < 8; nt++)
            #pragma unroll
            for (int c = 0; c < 4; c++) s[nt][c] = 0.f;
        #pragma unroll
        for (int kt = 0; kt < 8; kt++) {
            int kk = kt * 8;
            #pragma unroll
            for (int nt = 0; nt < 8; nt++) {
                unsigned b0 = __float_as_uint(Ks[(kk + t4) * PK + nt * 8 + g]);
                unsigned b1 = __float_as_uint(Ks[(kk + t4 + 4) * PK + nt * 8 + g]);
                mma_tf32(s[nt], qa[kt], b0, b1);
            }
        }

        // ---- online softmax (base-2; scale pre-folded into Wq) ----
        float mx0 = -INFINITY, mx1 = -INFINITY;
        #pragma unroll
        for (int nt = 0; nt < 8; nt++) {
            mx0 = fmaxf(mx0, fmaxf(s[nt][0], s[nt][1]));
            mx1 = fmaxf(mx1, fmaxf(s[nt][2], s[nt][3]));
        }
        mx0 = fmaxf(mx0, __shfl_xor_sync(0xffffffffu, mx0, 1));
        mx0 = fmaxf(mx0, __shfl_xor_sync(0xffffffffu, mx0, 2));
        mx1 = fmaxf(mx1, __shfl_xor_sync(0xffffffffu, mx1, 1));
        mx1 = fmaxf(mx1, __shfl_xor_sync(0xffffffffu, mx1, 2));
        float mn0 = fmaxf(m0, mx0), mn1 = fmaxf(m1, mx1);
        float c0 = ex2f(m0 - mn0), c1 = ex2f(m1 - mn1);
        float rs0 = 0.f, rs1 = 0.f;
        float* Ps = QPs;
        #pragma unroll
        for (int nt = 0; nt < 8; nt++) {
            float p00 = ex2f(s[nt][0] - mn0);
            float p01 = ex2f(s[nt][1] - mn0);
            float p10 = ex2f(s[nt][2] - mn1);
            float p11 = ex2f(s[nt][3] - mn1);
            rs0 += p00 + p01;
            rs1 += p10 + p11;
            int colc = nt * 8 + 2 * t4;
            *reinterpret_cast<float2*>(&Ps[row0 * PP + colc]) =
                make_float2(f2tff(p00), f2tff(p01));
            *reinterpret_cast<float2*>(&Ps[(row0 + 8) * PP + colc]) =
                make_float2(f2tff(p10), f2tff(p11));
        }
        rs0 += __shfl_xor_sync(0xffffffffu, rs0, 1);
        rs0 += __shfl_xor_sync(0xffffffffu, rs0, 2);
        rs1 += __shfl_xor_sync(0xffffffffu, rs1, 1);
        rs1 += __shfl_xor_sync(0xffffffffu, rs1, 2);
        ls0 = ls0 * c0 + rs0;
        ls1 = ls1 * c1 + rs1;
        m0 = mn0; m1 = mn1;
        #pragma unroll
        for (int nt = 0; nt < 8; nt++) {
            o[nt][0] *= c0; o[nt][1] *= c0;
            o[nt][2] *= c1; o[nt][3] *= c1;
        }
        __syncwarp();  // P rows are warp-local

        // ---- O += P V ----
        #pragma unroll
        for (int kt = 0; kt < 8; kt++) {
            int kk = kt * 8;
            unsigned a[4];
            a[0] = __float_as_uint(Ps[row0 * PP + kk + t4]);
            a[1] = __float_as_uint(Ps[(row0 + 8) * PP + kk + t4]);
            a[2] = __float_as_uint(Ps[row0 * PP + kk + t4 + 4]);
            a[3] = __float_as_uint(Ps[(row0 + 8) * PP + kk + t4 + 4]);
            #pragma unroll
            for (int nt = 0; nt < 8; nt++) {
                unsigned b0 = __float_as_uint(Vs[(nt * 8 + g) * PV + kk + t4]);
                unsigned b1 = __float_as_uint(Vs[(nt * 8 + g) * PV + kk + t4 + 4]);
                mma_tf32(o[nt], a, b0, b1);
            }
        }
        __syncthreads();  // all warps done with Ks/Vs before next tile's loads
    }

    // ---- normalize, stage O^T [d][i] (pad PV) in Ks region, write tf32 ----
    float inv0 = 1.f / ls0, inv1 = 1.f / ls1;
    float* Os = Ks;
    #pragma unroll
    for (int nt = 0; nt < 8; nt++) {
        int d = nt * 8 + 2 * t4;
        Os[(d    ) * PV + row0]     = f2tff(o[nt][0] * inv0);
        Os[(d + 1) * PV + row0]     = f2tff(o[nt][1] * inv0);
        Os[(d    ) * PV + row0 + 8] = f2tff(o[nt][2] * inv1);
        Os[(d + 1) * PV + row0 + 8] = f2tff(o[nt][3] * inv1);
    }
    __syncthreads();
    const size_t cbase = (size_t)n * CC + h * DH;
    #pragma unroll
    for (int r = 0; r < 8; r++) {
        int idx = r * 512 + tid * 4;
        int d = idx >> 6, i = idx & 63;
        float4 val = *reinterpret_cast<const float4*>(&Os[d * PV + i]);
        *reinterpret_cast<float4*>(&ao[(cbase + d) * LL + l0 + i]) = val;
    }
}

// ---------------------------------------------------------------------------
extern "C" void kernel_launch(void* const* d_in, const int* in_sizes, int n_in,
                              void* d_out, int out_size) {
    const float* x     = (const float*)d_in[0];
    const float* gamma = (const float*)d_in[1];
    const float* beta  = (const float*)d_in[2];
    const float* Wq    = (const float*)d_in[3];
    const float* Wk    = (const float*)d_in[4];
    const float* Wv    = (const float*)d_in[5];
    const float* Wp    = (const float*)d_in[6];
    const float* bp    = (const float*)d_in[7];
    float* out = (float*)d_out;

    static float *xn = nullptr, *q, *k, *v, *ao, *wt;
    static size_t attn_smem =
        (size_t)(64 * PK + 64 * PV + 64 * PK) * sizeof(float);  // 54272 B
    if (!xn) {
        cudaGetSymbolAddress((void**)&xn, g_xn);
        cudaGetSymbolAddress((void**)&q,  g_q);
        cudaGetSymbolAddress((void**)&k,  g_k);
        cudaGetSymbolAddress((void**)&v,  g_v);
        cudaGetSymbolAddress((void**)&ao, g_ao);
        cudaGetSymbolAddress((void**)&wt, g_wt);
        cudaFuncSetAttribute(attn_tc_kernel,
                             cudaFuncAttributeMaxDynamicSharedMemorySize,
                             (int)attn_smem);
    }

    // Weight tf32 prep (+Wq scaling) + GroupNorm (independent)
    wcvt_kernel<<<CC * CC / (256 * 4), 256>>>(Wq, Wk, Wv, Wp, wt);
    gn_kernel<<<NB * GROUPS, 256>>>(x, gamma, beta, xn);

    // Fused QKV projection (tensor cores, outputs tf32-rounded)
    dim3 pgrid(LL / 64, CC / 64, NB);
    qkv_tc_kernel<<<pgrid, 128>>>(xn, wt, q, k, v);

    // Flash attention (tensor cores, CVT-free cp.async loads, 4 blocks/SM)
    attn_tc_kernel<<<dim3(LL / 64, NB * HEADS), 128, attn_smem>>>(q, k, v, ao);

    // Output projection (+bias) straight into d_out (tensor cores)
    oproj_tc_kernel<<<pgrid, 128>>>(ao, wt + 3 * CC * CC, bp, out);
}

// round 8
// speedup vs baseline: 2.1796x; 1.8144x over previous
#include <cuda_runtime.h>
#include <cuda_fp16.h>
#include <math.h>

#define NB 4
#define CC 256
#define HEADS 4
#define DH 64
#define LL 4096
#define GROUPS 32

// Scratch (allocation-free rule: __device__ globals)
__device__ float  g_xn[NB * CC * LL];
__device__ __half g_qh[NB * HEADS * LL * DH];   // [n][h][l][d]
__device__ __half g_kh[NB * HEADS * LL * DH];   // [n][h][l][d]
__device__ __half g_vh[NB * HEADS * DH * LL];   // [n][h][d][l]
__device__ float  g_ao[NB * CC * LL];
__device__ float  g_wt[4 * CC * CC];            // tf32 Wq(*scale),Wk,Wv,Wp

// ---------------------------------------------------------------------------
// helpers
// ---------------------------------------------------------------------------
__device__ __forceinline__ unsigned f2tf(float x) {
    unsigned u;
    asm("cvt.rna.tf32.f32 %0, %1;" : "=r"(u) : "f"(x));
    return u;
}
__device__ __forceinline__ float f2tff(float x) { return __uint_as_float(f2tf(x)); }
__device__ __forceinline__ float ex2f(float x) {
    float r;
    asm("ex2.approx.ftz.f32 %0, %1;" : "=f"(r) : "f"(x));
    return r;
}
__device__ __forceinline__ void mma_tf32(float* c, const unsigned* a,
                                         unsigned b0, unsigned b1) {
    asm volatile(
        "mma.sync.aligned.m16n8k8.row.col.f32.tf32.tf32.f32 "
        "{%0,%1,%2,%3}, {%4,%5,%6,%7}, {%8,%9}, {%0,%1,%2,%3};"
        : "+f"(c[0]), "+f"(c[1]), "+f"(c[2]), "+f"(c[3])
        : "r"(a[0]), "r"(a[1]), "r"(a[2]), "r"(a[3]), "r"(b0), "r"(b1));
}
__device__ __forceinline__ void mma_f16(float* c, const unsigned* a,
                                        unsigned b0, unsigned b1) {
    asm volatile(
        "mma.sync.aligned.m16n8k16.row.col.f32.f16.f16.f32 "
        "{%0,%1,%2,%3}, {%4,%5,%6,%7}, {%8,%9}, {%0,%1,%2,%3};"
        : "+f"(c[0]), "+f"(c[1]), "+f"(c[2]), "+f"(c[3])
        : "r"(a[0]), "r"(a[1]), "r"(a[2]), "r"(a[3]), "r"(b0), "r"(b1));
}
__device__ __forceinline__ void cp16(void* smem_dst, const void* gmem_src) {
    unsigned sa = (unsigned)__cvta_generic_to_shared(smem_dst);
    asm volatile("cp.async.ca.shared.global [%0], [%1], 16;"
                 :: "r"(sa), "l"(gmem_src) : "memory");
}

// ---------------------------------------------------------------------------
// Weight prep: tf32-round; Wq pre-scaled by dh^-0.5 * log2(e).
// ---------------------------------------------------------------------------
__global__ void wcvt_kernel(const float* __restrict__ Wq, const float* __restrict__ Wk,
                            const float* __restrict__ Wv, const float* __restrict__ Wp,
                            float* __restrict__ wt) {
    const float qscale = 0.125f * 1.44269504088896340736f;
    int i4 = (blockIdx.x * 256 + threadIdx.x) * 4;
    {
        float4 w = *reinterpret_cast<const float4*>(&Wq[i4]);
        *reinterpret_cast<float4*>(&wt[i4]) =
            make_float4(f2tff(w.x * qscale), f2tff(w.y * qscale),
                        f2tff(w.z * qscale), f2tff(w.w * qscale));
    }
    const float* src[3] = {Wk, Wv, Wp};
    #pragma unroll
    for (int m = 0; m < 3; m++) {
        float4 w = *reinterpret_cast<const float4*>(&src[m][i4]);
        *reinterpret_cast<float4*>(&wt[(m + 1) * CC * CC + i4]) =
            make_float4(f2tff(w.x), f2tff(w.y), f2tff(w.z), f2tff(w.w));
    }
}

// ---------------------------------------------------------------------------
// GroupNorm: one block per (n, group). Output tf32-rounded.
// ---------------------------------------------------------------------------
__global__ void gn_kernel(const float* __restrict__ x,
                          const float* __restrict__ gamma,
                          const float* __restrict__ beta,
                          float* __restrict__ xn) {
    int n = blockIdx.x >> 5;
    int g = blockIdx.x & 31;
    const float* xp = x  + (size_t)(n * CC + g * 8) * LL;
    float*       op = xn + (size_t)(n * CC + g * 8) * LL;

    float s = 0.f, ss = 0.f;
    for (int i = threadIdx.x; i < 8 * LL; i += 256) {
        float v = xp[i];
        s += v; ss += v * v;
    }
    __shared__ float rs[256], rss[256];
    rs[threadIdx.x] = s; rss[threadIdx.x] = ss;
    __syncthreads();
    for (int o = 128; o > 0; o >>= 1) {
        if (threadIdx.x < o) {
            rs[threadIdx.x]  += rs[threadIdx.x + o];
            rss[threadIdx.x] += rss[threadIdx.x + o];
        }
        __syncthreads();
    }
    const float invN = 1.f / (8.f * LL);
    float mean = rs[0] * invN;
    float var  = rss[0] * invN - mean * mean;
    float inv  = rsqrtf(var + 1e-5f);
    for (int i = threadIdx.x; i < 8 * LL; i += 256) {
        int c = g * 8 + (i >> 12);
        op[i] = f2tff((xp[i] - mean) * inv * gamma[c] + beta[c]);
    }
}

// ---------------------------------------------------------------------------
// Fused QKV projection (tf32 tensor cores). Epilogue emits __half in
// attention-friendly layouts: Q,K -> [n][h][l][d], V -> [n][h][d][l].
// ---------------------------------------------------------------------------
__global__ void __launch_bounds__(128) qkv_tc_kernel(
        const float* __restrict__ xn, const float* __restrict__ wt,
        __half* __restrict__ qh, __half* __restrict__ kh, __half* __restrict__ vh) {
    __shared__ float Xs[32 * 72];
    __shared__ float Ws[3][64 * 40];

    int n  = blockIdx.z;
    int o0 = blockIdx.y << 6;
    int l0 = blockIdx.x << 6;
    const float* xb = xn + (size_t)n * CC * LL;

    int tid = threadIdx.x;
    int lane = tid & 31, w = tid >> 5;
    int g = lane >> 2, t4 = lane & 3;

    float acc[3][8][4];
    #pragma unroll
    for (int m = 0; m < 3; m++)
        #pragma unroll
        for (int nt = 0; nt < 8; nt++)
            #pragma unroll
            for (int c = 0; c < 4; c++) acc[m][nt][c] = 0.f;

    for (int c0 = 0; c0 < CC; c0 += 32) {
        __syncthreads();
        #pragma unroll
        for (int r = 0; r < 4; r++) {
            int idx = r * 512 + tid * 4;
            int cc = idx >> 6, ll = idx & 63;
            float4 xv = *reinterpret_cast<const float4*>(&xb[(size_t)(c0 + cc) * LL + l0 + ll]);
            *reinterpret_cast<float4*>(&Xs[cc * 72 + ll]) = xv;
        }
        #pragma unroll
        for (int m = 0; m < 3; m++) {
            const float* Wm = wt + m * CC * CC;
            #pragma unroll
            for (int p = 0; p < 4; p++) {
                int oo = (tid >> 3) + p * 16;
                int cc4 = (tid & 7) * 4;
                float4 wv = *reinterpret_cast<const float4*>(&Wm[(o0 + oo) * CC + c0 + cc4]);
                *reinterpret_cast<float4*>(&Ws[m][oo * 40 + cc4]) = wv;
            }
        }
        __syncthreads();

        #pragma unroll
        for (int kt = 0; kt < 4; kt++) {
            int kk = kt * 8;
            unsigned a[3][4];
            #pragma unroll
            for (int m = 0; m < 3; m++) {
                a[m][0] = __float_as_uint(Ws[m][(w * 16 + g) * 40 + kk + t4]);
                a[m][1] = __float_as_uint(Ws[m][(w * 16 + g + 8) * 40 + kk + t4]);
                a[m][2] = __float_as_uint(Ws[m][(w * 16 + g) * 40 + kk + t4 + 4]);
                a[m][3] = __float_as_uint(Ws[m][(w * 16 + g + 8) * 40 + kk + t4 + 4]);
            }
            #pragma unroll
            for (int nt = 0; nt < 8; nt++) {
                unsigned b0 = __float_as_uint(Xs[(kk + t4) * 72 + nt * 8 + g]);
                unsigned b1 = __float_as_uint(Xs[(kk + t4 + 4) * 72 + nt * 8 + g]);
                mma_tf32(acc[0][nt], a[0], b0, b1);
                mma_tf32(acc[1][nt], a[1], b0, b1);
                mma_tf32(acc[2][nt], a[2], b0, b1);
            }
        }
    }

    int orow = o0 + w * 16 + g;
    int h = orow >> 6, d0 = orow & 63;
    size_t nhb = (size_t)(n * HEADS + h);
    __half* qd = qh + nhb * LL * DH;
    __half* kd = kh + nhb * LL * DH;
    __half* vd = vh + nhb * DH * LL;

    #pragma unroll
    for (int nt = 0; nt < 8; nt++) {
        int l = l0 + nt * 8 + 2 * t4;
        // Q,K: [l][d] scattered 2B stores
        qd[(size_t)l * DH + d0]           = __float2half_rn(acc[0][nt][0]);
        qd[(size_t)(l + 1) * DH + d0]     = __float2half_rn(acc[0][nt][1]);
        qd[(size_t)l * DH + d0 + 8]       = __float2half_rn(acc[0][nt][2]);
        qd[(size_t)(l + 1) * DH + d0 + 8] = __float2half_rn(acc[0][nt][3]);
        kd[(size_t)l * DH + d0]           = __float2half_rn(acc[1][nt][0]);
        kd[(size_t)(l + 1) * DH + d0]     = __float2half_rn(acc[1][nt][1]);
        kd[(size_t)l * DH + d0 + 8]       = __float2half_rn(acc[1][nt][2]);
        kd[(size_t)(l + 1) * DH + d0 + 8] = __float2half_rn(acc[1][nt][3]);
        // V: [d][l] half2 stores (adjacent l)
        *reinterpret_cast<__half2*>(&vd[(size_t)d0 * LL + l]) =
            __floats2half2_rn(acc[2][nt][0], acc[2][nt][1]);
        *reinterpret_cast<__half2*>(&vd[(size_t)(d0 + 8) * LL + l]) =
            __floats2half2_rn(acc[2][nt][2], acc[2][nt][3]);
    }
}

// ---------------------------------------------------------------------------
// Output projection (tf32) + bias, writes d_out. (unchanged)
// ---------------------------------------------------------------------------
__global__ void __launch_bounds__(128) oproj_tc_kernel(
        const float* __restrict__ ao, const float* __restrict__ wt,
        const float* __restrict__ bias, float* __restrict__ out) {
    __shared__ float Xs[32 * 72];
    __shared__ float Ws[64 * 40];

    int n  = blockIdx.z;
    int o0 = blockIdx.y << 6;
    int l0 = blockIdx.x << 6;
    const float* xb = ao + (size_t)n * CC * LL;

    int tid = threadIdx.x;
    int lane = tid & 31, w = tid >> 5;
    int g = lane >> 2, t4 = lane & 3;

    float acc[8][4];
    #pragma unroll
    for (int nt = 0; nt < 8; nt++)
        #pragma unroll
        for (int c = 0; c < 4; c++) acc[nt][c] = 0.f;

    for (int c0 = 0; c0 < CC; c0 += 32) {
        __syncthreads();
        #pragma unroll
        for (int r = 0; r < 4; r++) {
            int idx = r * 512 + tid * 4;
            int cc = idx >> 6, ll = idx & 63;
            float4 xv = *reinterpret_cast<const float4*>(&xb[(size_t)(c0 + cc) * LL + l0 + ll]);
            *reinterpret_cast<float4*>(&Xs[cc * 72 + ll]) = xv;
        }
        #pragma unroll
        for (int p = 0; p < 4; p++) {
            int oo = (tid >> 3) + p * 16;
            int cc4 = (tid & 7) * 4;
            float4 wv = *reinterpret_cast<const float4*>(&wt[(o0 + oo) * CC + c0 + cc4]);
            *reinterpret_cast<float4*>(&Ws[oo * 40 + cc4]) = wv;
        }
        __syncthreads();

        #pragma unroll
        for (int kt = 0; kt < 4; kt++) {
            int kk = kt * 8;
            unsigned a[4];
            a[0] = __float_as_uint(Ws[(w * 16 + g) * 40 + kk + t4]);
            a[1] = __float_as_uint(Ws[(w * 16 + g + 8) * 40 + kk + t4]);
            a[2] = __float_as_uint(Ws[(w * 16 + g) * 40 + kk + t4 + 4]);
            a[3] = __float_as_uint(Ws[(w * 16 + g + 8) * 40 + kk + t4 + 4]);
            #pragma unroll
            for (int nt = 0; nt < 8; nt++) {
                unsigned b0 = __float_as_uint(Xs[(kk + t4) * 72 + nt * 8 + g]);
                unsigned b1 = __float_as_uint(Xs[(kk + t4 + 4) * 72 + nt * 8 + g]);
                mma_tf32(acc[nt], a, b0, b1);
            }
        }
    }

    int orow = o0 + w * 16 + g;
    float bb0 = bias[orow], bb1 = bias[orow + 8];
    float* op = out + (size_t)n * CC * LL;
    #pragma unroll
    for (int nt = 0; nt < 8; nt++) {
        size_t base = (size_t)orow * LL + l0 + nt * 8 + 2 * t4;
        *reinterpret_cast<float2*>(&op[base]) =
            make_float2(acc[nt][0] + bb0, acc[nt][1] + bb0);
        *reinterpret_cast<float2*>(&op[base + 8 * LL]) =
            make_float2(acc[nt][2] + bb1, acc[nt][3] + bb1);
    }
}

// ---------------------------------------------------------------------------
// Flash attention, fp16 mma m16n8k16 (f32 accum). 4 warps x 16 rows.
// Smem tiles: Ks [j][d], Vs [d][j], QPs (Q [i][d] then P [i][j]),
// all 64 x 72 halves (144B rows). All fragment loads = conflict-free LDS.32.
// ---------------------------------------------------------------------------
#define PH 72
#define NT (LL / 64)

__global__ void __launch_bounds__(128) attn_f16_kernel(
        const __half* __restrict__ q, const __half* __restrict__ k,
        const __half* __restrict__ v, float* __restrict__ ao) {
    extern __shared__ __align__(16) char smc[];
    __half* Ks  = reinterpret_cast<__half*>(smc);
    __half* Vs  = Ks + 64 * PH;
    __half* QPs = Vs + 64 * PH;
    float*  Osf = reinterpret_cast<float*>(smc);   // epilogue staging [d][i] pad 68

    int nh = blockIdx.y;
    int l0 = blockIdx.x << 6;
    const __half* qb = q + (size_t)nh * LL * DH;
    const __half* kb = k + (size_t)nh * LL * DH;
    const __half* vb = v + (size_t)nh * DH * LL;

    int tid  = threadIdx.x;
    int lane = tid & 31, w = tid >> 5;
    int g = lane >> 2, t4 = lane & 3;
    int row0 = w * 16 + g;

    // ---- Q tile -> QPs[i][d] (512 x 16B chunks) ----
    #pragma unroll
    for (int r = 0; r < 4; r++) {
        int cix = r * 128 + tid;
        int row = cix >> 3, c8 = (cix & 7) * 8;
        cp16(&QPs[row * PH + c8], &qb[(size_t)(l0 + row) * DH + c8]);
    }
    asm volatile("cp.async.commit_group;" ::: "memory");
    asm volatile("cp.async.wait_group 0;" ::: "memory");
    __syncthreads();

    // Q fragments (A of m16n8k16): qa[kt][4], kt over 4 k-chunks of 16
    unsigned qa[4][4];
    #pragma unroll
    for (int kt = 0; kt < 4; kt++) {
        int kk = kt * 16 + 2 * t4;
        qa[kt][0] = *reinterpret_cast<unsigned*>(&QPs[row0 * PH + kk]);
        qa[kt][1] = *reinterpret_cast<unsigned*>(&QPs[(row0 + 8) * PH + kk]);
        qa[kt][2] = *reinterpret_cast<unsigned*>(&QPs[row0 * PH + kk + 8]);
        qa[kt][3] = *reinterpret_cast<unsigned*>(&QPs[(row0 + 8) * PH + kk + 8]);
    }
    __syncthreads();  // QPs now reusable as Ps

    float m0 = -INFINITY, m1 = -INFINITY, ls0 = 0.f, ls1 = 0.f;
    float o[8][4];
    #pragma unroll
    for (int nt = 0; nt < 8; nt++)
        #pragma unroll
        for (int c = 0; c < 4; c++) o[nt][c] = 0.f;

    for (int jt = 0; jt < NT; jt++) {
        int lk = jt << 6;
        // ---- K,V tiles ----
        #pragma unroll
        for (int r = 0; r < 4; r++) {
            int cix = r * 128 + tid;
            int row = cix >> 3, c8 = (cix & 7) * 8;
            cp16(&Ks[row * PH + c8], &kb[(size_t)(lk + row) * DH + c8]);
            cp16(&Vs[row * PH + c8], &vb[(size_t)row * LL + lk + c8]);
        }
        asm volatile("cp.async.commit_group;" ::: "memory");
        asm volatile("cp.async.wait_group 0;" ::: "memory");
        __syncthreads();

        // ---- S = Q K^T ----
        float s[8][4];
        #pragma unroll
        for (int nt = 0; nt < 8; nt++)
            #pragma unroll
            for (int c = 0; c < 4; c++) s[nt][c] = 0.f;
        #pragma unroll
        for (int kt = 0; kt < 4; kt++) {
            int kk = kt * 16 + 2 * t4;
            #pragma unroll
            for (int nt = 0; nt < 8; nt++) {
                int col = nt * 8 + g;
                unsigned b0 = *reinterpret_cast<const unsigned*>(&Ks[col * PH + kk]);
                unsigned b1 = *reinterpret_cast<const unsigned*>(&Ks[col * PH + kk + 8]);
                mma_f16(s[nt], qa[kt], b0, b1);
            }
        }

        // ---- online softmax (base-2; scale pre-folded into Wq) ----
        float mx0 = -INFINITY, mx1 = -INFINITY;
        #pragma unroll
        for (int nt = 0; nt < 8; nt++) {
            mx0 = fmaxf(mx0, fmaxf(s[nt][0], s[nt][1]));
            mx1 = fmaxf(mx1, fmaxf(s[nt][2], s[nt][3]));
        }
        mx0 = fmaxf(mx0, __shfl_xor_sync(0xffffffffu, mx0, 1));
        mx0 = fmaxf(mx0, __shfl_xor_sync(0xffffffffu, mx0, 2));
        mx1 = fmaxf(mx1, __shfl_xor_sync(0xffffffffu, mx1, 1));
        mx1 = fmaxf(mx1, __shfl_xor_sync(0xffffffffu, mx1, 2));
        float mn0 = fmaxf(m0, mx0), mn1 = fmaxf(m1, mx1);
        float c0 = ex2f(m0 - mn0), c1 = ex2f(m1 - mn1);
        float rs0 = 0.f, rs1 = 0.f;
        __half* Ps = QPs;
        #pragma unroll
        for (int nt = 0; nt < 8; nt++) {
            float p00 = ex2f(s[nt][0] - mn0);
            float p01 = ex2f(s[nt][1] - mn0);
            float p10 = ex2f(s[nt][2] - mn1);
            float p11 = ex2f(s[nt][3] - mn1);
            rs0 += p00 + p01;
            rs1 += p10 + p11;
            int colc = nt * 8 + 2 * t4;
            *reinterpret_cast<__half2*>(&Ps[row0 * PH + colc]) =
                __floats2half2_rn(p00, p01);
            *reinterpret_cast<__half2*>(&Ps[(row0 + 8) * PH + colc]) =
                __floats2half2_rn(p10, p11);
        }
        rs0 += __shfl_xor_sync(0xffffffffu, rs0, 1);
        rs0 += __shfl_xor_sync(0xffffffffu, rs0, 2);
        rs1 += __shfl_xor_sync(0xffffffffu, rs1, 1);
        rs1 += __shfl_xor_sync(0xffffffffu, rs1, 2);
        ls0 = ls0 * c0 + rs0;
        ls1 = ls1 * c1 + rs1;
        m0 = mn0; m1 = mn1;
        #pragma unroll
        for (int nt = 0; nt < 8; nt++) {
            o[nt][0] *= c0; o[nt][1] *= c0;
            o[nt][2] *= c1; o[nt][3] *= c1;
        }
        __syncwarp();  // P rows are warp-local

        // ---- O += P V^T (B[k=j][n=d] = Vs[d][j]) ----
        #pragma unroll
        for (int kt = 0; kt < 4; kt++) {
            int kk = kt * 16 + 2 * t4;
            unsigned a[4];
            a[0] = *reinterpret_cast<const unsigned*>(&Ps[row0 * PH + kk]);
            a[1] = *reinterpret_cast<const unsigned*>(&Ps[(row0 + 8) * PH + kk]);
            a[2] = *reinterpret_cast<const unsigned*>(&Ps[row0 * PH + kk + 8]);
            a[3] = *reinterpret_cast<const unsigned*>(&Ps[(row0 + 8) * PH + kk + 8]);
            #pragma unroll
            for (int nt = 0; nt < 8; nt++) {
                int col = nt * 8 + g;
                unsigned b0 = *reinterpret_cast<const unsigned*>(&Vs[col * PH + kk]);
                unsigned b1 = *reinterpret_cast<const unsigned*>(&Vs[col * PH + kk + 8]);
                mma_f16(o[nt], a, b0, b1);
            }
        }
        __syncthreads();  // done with Ks/Vs/Ps before next tile
    }

    // ---- normalize, stage O^T f32 [d][i] pad 68 (overlaps Ks+Vs), write ----
    float inv0 = 1.f / ls0, inv1 = 1.f / ls1;
    #pragma unroll
    for (int nt = 0; nt < 8; nt++) {
        int d = nt * 8 + 2 * t4;
        Osf[(d    ) * 68 + row0]     = o[nt][0] * inv0;
        Osf[(d + 1) * 68 + row0]     = o[nt][1] * inv0;
        Osf[(d    ) * 68 + row0 + 8] = o[nt][2] * inv1;
        Osf[(d + 1) * 68 + row0 + 8] = o[nt][3] * inv1;
    }
    __syncthreads();
    #pragma unroll
    for (int r = 0; r < 8; r++) {
        int idx = r * 512 + tid * 4;
        int d = idx >> 6, i = idx & 63;
        float4 val = *reinterpret_cast<const float4*>(&Osf[d * 68 + i]);
        *reinterpret_cast<float4*>(&ao[((size_t)(nh * 64 + d)) * LL + l0 + i]) = val;
    }
}

// ---------------------------------------------------------------------------
extern "C" void kernel_launch(void* const* d_in, const int* in_sizes, int n_in,
                              void* d_out, int out_size) {
    const float* x     = (const float*)d_in[0];
    const float* gamma = (const float*)d_in[1];
    const float* beta  = (const float*)d_in[2];
    const float* Wq    = (const float*)d_in[3];
    const float* Wk    = (const float*)d_in[4];
    const float* Wv    = (const float*)d_in[5];
    const float* Wp    = (const float*)d_in[6];
    const float* bp    = (const float*)d_in[7];
    float* out = (float*)d_out;

    static float *xn = nullptr, *ao, *wt;
    static __half *qh, *kh, *vh;
    static size_t attn_smem = (size_t)(3 * 64 * PH) * sizeof(__half);  // 27648 B
    if (!xn) {
        cudaGetSymbolAddress((void**)&xn, g_xn);
        cudaGetSymbolAddress((void**)&qh, g_qh);
        cudaGetSymbolAddress((void**)&kh, g_kh);
        cudaGetSymbolAddress((void**)&vh, g_vh);
        cudaGetSymbolAddress((void**)&ao, g_ao);
        cudaGetSymbolAddress((void**)&wt, g_wt);
        cudaFuncSetAttribute(attn_f16_kernel,
                             cudaFuncAttributeMaxDynamicSharedMemorySize,
                             (int)attn_smem);
    }

    // Weight tf32 prep (+Wq scaling) + GroupNorm (independent)
    wcvt_kernel<<<CC * CC / (256 * 4), 256>>>(Wq, Wk, Wv, Wp, wt);
    gn_kernel<<<NB * GROUPS, 256>>>(x, gamma, beta, xn);

    // Fused QKV projection (tf32 cores, f16 outputs in attention layouts)
    dim3 pgrid(LL / 64, CC / 64, NB);
    qkv_tc_kernel<<<pgrid, 128>>>(xn, wt, qh, kh, vh);

    // Flash attention (fp16 m16n8k16, f32 accumulate)
    attn_f16_kernel<<<dim3(LL / 64, NB * HEADS), 128, attn_smem>>>(qh, kh, vh, ao);

    // Output projection (+bias) straight into d_out (tf32 cores)
    oproj_tc_kernel<<<pgrid, 128>>>(ao, wt + 3 * CC * CC, bp, out);
}